// round 15
// baseline (speedup 1.0000x reference)
#include <cuda_runtime.h>
#include <stdint.h>

// Problem constants (fixed shapes from reference: B=8, K=4, N=131072)
#define T_TOTAL   4194304      // B*K*N
#define NCHUNK    32768        // per-128-element chunks
#define NT        256
#define NEG_IDLE_F (-100000000.0f)
#define NEG_FILL_F (-1000.0f)

// Scratch (device globals — no allocation allowed in kernel_launch)
__device__ unsigned g_sum128[NCHUNK];   // packed per-128 sums (s | a<<16)
__device__ int      g_woff_s[NCHUNK];   // per-chunk global exclusive offsets
__device__ int      g_woff_a[NCHUNK];

// ---------------------------------------------------------------------------
// Kernel 1: count both masks at 128-element granularity. Each thread owns 16
// contiguous elems; groups of 8 lanes reduce to one 128-elem chunk sum.
// No smem, no barriers.
// ---------------------------------------------------------------------------
__global__ __launch_bounds__(NT) void k_count(const uint32_t* __restrict__ ms,
                                              const uint32_t* __restrict__ ma) {
    int blk = blockIdx.x, tid = threadIdx.x;
    size_t e0 = (size_t)blk * 4096 + (size_t)tid * 16;
    const uint4* s4 = reinterpret_cast<const uint4*>(ms + e0);
    const uint4* a4 = reinterpret_cast<const uint4*>(ma + e0);

    int cs = 0, ca = 0;
    #pragma unroll
    for (int i = 0; i < 4; i++) {
        uint4 s = s4[i], a = a4[i];
        cs += (s.x != 0) + (s.y != 0) + (s.z != 0) + (s.w != 0);
        ca += (a.x != 0) + (a.y != 0) + (a.z != 0) + (a.w != 0);
    }
    int p = cs | (ca << 16);
    // Reduce within aligned groups of 8 lanes (= 128 contiguous elems).
    p += __shfl_xor_sync(0xffffffffu, p, 1);
    p += __shfl_xor_sync(0xffffffffu, p, 2);
    p += __shfl_xor_sync(0xffffffffu, p, 4);
    if ((tid & 7) == 0)
        g_sum128[blk * 32 + (tid >> 3)] = (unsigned)p;
}

// ---------------------------------------------------------------------------
// Kernel 2: exclusive scan of 32768 packed chunk sums -> per-chunk offsets.
// One block, 1024 threads, 32 chunks each (packed local scan fits 16 bits:
// 32*128 = 4096 < 65536).
// ---------------------------------------------------------------------------
__global__ __launch_bounds__(1024) void k_scan() {
    int tid = threadIdx.x, lane = tid & 31, w = tid >> 5;
    unsigned loc[32];
    int ss = 0, sa = 0;
    #pragma unroll
    for (int i = 0; i < 32; i++) {
        unsigned pw = g_sum128[tid * 32 + i];
        loc[i] = (unsigned)ss | ((unsigned)sa << 16);
        ss += (int)(pw & 0xffffu);
        sa += (int)(pw >> 16);
    }
    // Block exclusive scan of (ss, sa).
    int is = ss, ia = sa;
    #pragma unroll
    for (int o = 1; o < 32; o <<= 1) {
        int t = __shfl_up_sync(0xffffffffu, is, o); if (lane >= o) is += t;
        t     = __shfl_up_sync(0xffffffffu, ia, o); if (lane >= o) ia += t;
    }
    __shared__ int ws[32], wa[32];
    if (lane == 31) { ws[w] = is; wa[w] = ia; }
    __syncthreads();
    if (w == 0) {
        int ts = ws[lane], ta = wa[lane];
        int js = ts, ja = ta;
        #pragma unroll
        for (int o = 1; o < 32; o <<= 1) {
            int t = __shfl_up_sync(0xffffffffu, js, o); if (lane >= o) js += t;
            t     = __shfl_up_sync(0xffffffffu, ja, o); if (lane >= o) ja += t;
        }
        ws[lane] = js - ts;
        wa[lane] = ja - ta;
    }
    __syncthreads();
    int base_s = ws[w] + is - ss;
    int base_a = wa[w] + ia - sa;
    #pragma unroll
    for (int i = 0; i < 32; i++) {
        g_woff_s[tid * 32 + i] = base_s + (int)(loc[i] & 0xffffu);
        g_woff_a[tid * 32 + i] = base_a + (int)(loc[i] >> 16);
    }
}

// ---------------------------------------------------------------------------
// Kernel 3: expansion with 1M threads, 4 elems/thread, warp-per-128-chunk.
// Per thread: 2 mask uint4 loads -> 5-shfl scan -> 4 independent gathers ->
// 3 coalesced float4 stores. No smem, no barriers, no loop-carried state.
// ---------------------------------------------------------------------------
__global__ __launch_bounds__(NT) void k_main(
    const uint32_t* __restrict__ ms, const uint32_t* __restrict__ ma,
    const float* __restrict__ rgb, const float* __restrict__ ls,
    const float* __restrict__ la,  const float* __restrict__ idle_st,
    float* __restrict__ rgb_out, float* __restrict__ ls_out,
    float* __restrict__ la_out) {

    int tid = threadIdx.x;
    int lane = tid & 31, w = tid >> 5;
    int c = blockIdx.x * 8 + w;            // chunk id, 0..32767 (128 elems each)
    size_t e0 = (size_t)c * 128 + (size_t)lane * 4;

    uint4 s = *reinterpret_cast<const uint4*>(ms + e0);
    uint4 a = *reinterpret_cast<const uint4*>(ma + e0);
    unsigned mS = (s.x != 0u) | ((s.y != 0u) << 1) | ((s.z != 0u) << 2) | ((s.w != 0u) << 3);
    unsigned mA = (a.x != 0u) | ((a.y != 0u) << 1) | ((a.z != 0u) << 2) | ((a.w != 0u) << 3);

    // Packed warp scan (fields <= 128, safe in 16 bits).
    int p = __popc(mS) | (__popc(mA) << 16);
    int ip = p;
    #pragma unroll
    for (int o = 1; o < 32; o <<= 1) {
        int t = __shfl_up_sync(0xffffffffu, ip, o);
        if (lane >= o) ip += t;
    }
    int ep = ip - p;
    int base_s = g_woff_s[c] + (ep & 0xffff);
    int base_a = g_woff_a[c] + (ep >> 16);

    float idle   = idle_st[c >> 10];       // 1024 chunks per (b,k) row
    float scale  = 1.0f - idle;
    float negadd = idle * NEG_IDLE_F;

    float os[4], oa[4], ro[12];
    #pragma unroll
    for (int q = 0; q < 4; q++) {
        if ((mS >> q) & 1u) {
            int idx = base_s + __popc(mS & ((1u << q) - 1u));
            os[q] = __ldg(ls + idx) * scale + negadd;
            const float* rp = rgb + (size_t)idx * 3;
            ro[q * 3 + 0] = __ldg(rp + 0) * scale;
            ro[q * 3 + 1] = __ldg(rp + 1) * scale;
            ro[q * 3 + 2] = __ldg(rp + 2) * scale;
        } else {
            os[q] = NEG_FILL_F;
            ro[q * 3 + 0] = 0.0f; ro[q * 3 + 1] = 0.0f; ro[q * 3 + 2] = 0.0f;
        }
        if ((mA >> q) & 1u) {
            int idx = base_a + __popc(mA & ((1u << q) - 1u));
            oa[q] = __ldg(la + idx) * scale + negadd;
        } else {
            oa[q] = NEG_FILL_F;
        }
    }

    // Coalesced stores: warp covers 512B (ls/la) and 1.5KB (rgb) contiguous.
    *reinterpret_cast<float4*>(ls_out + e0) = make_float4(os[0], os[1], os[2], os[3]);
    *reinterpret_cast<float4*>(la_out + e0) = make_float4(oa[0], oa[1], oa[2], oa[3]);
    float4* rout = reinterpret_cast<float4*>(rgb_out + e0 * 3);
    rout[0] = make_float4(ro[0], ro[1],  ro[2],  ro[3]);
    rout[1] = make_float4(ro[4], ro[5],  ro[6],  ro[7]);
    rout[2] = make_float4(ro[8], ro[9],  ro[10], ro[11]);
}

// ---------------------------------------------------------------------------
// Launch: 3 kernels (count, scan, wide expand). Graph-capturable.
// ---------------------------------------------------------------------------
extern "C" void kernel_launch(void* const* d_in, const int* in_sizes, int n_in,
                              void* d_out, int out_size) {
    const float*    rgb  = (const float*)d_in[0];
    const float*    ls   = (const float*)d_in[1];
    const float*    la   = (const float*)d_in[2];
    const uint32_t* msf  = (const uint32_t*)d_in[3];
    const uint32_t* maf  = (const uint32_t*)d_in[4];
    const float*    idle = (const float*)d_in[5];

    float* out     = (float*)d_out;
    float* rgb_out = out;
    float* ls_out  = out + (size_t)T_TOTAL * 3;
    float* la_out  = ls_out + T_TOTAL;

    k_count<<<1024, NT>>>(msf, maf);
    k_scan<<<1, 1024>>>();
    k_main<<<4096, NT>>>(msf, maf, rgb, ls, la, idle, rgb_out, ls_out, la_out);
}

// round 16
// speedup vs baseline: 1.9967x; 1.9967x over previous
#include <cuda_runtime.h>
#include <stdint.h>

// Problem constants (fixed shapes from reference: B=8, K=4, N=131072)
#define T_TOTAL   4194304      // B*K*N
#define TILE      4096         // expansion tile (8 warps x 512)
#define NBLK      1024         // T_TOTAL / TILE
#define TILE_P    8192         // pack-kernel tile (2 chunks of 4096)
#define NBLK_P    512
#define NT        256
#define NWARP     (T_TOTAL / 512)   // 8192 warp-chunks of 512 elems
#define NEG_IDLE_F (-100000000.0f)
#define NEG_FILL_F (-1000.0f)

// Scratch (device globals — no allocation allowed in kernel_launch)
__device__ unsigned g_wsum[NWARP];            // packed per-warp-chunk sums (s | a<<16)
__device__ int      g_woff_s[NWARP];          // per-warp-chunk global exclusive offsets
__device__ int      g_woff_a[NWARP];
__device__ unsigned g_packed[T_TOTAL / 16];   // 1MB: 16 surf bits | 16 air bits

// ---------------------------------------------------------------------------
// Kernel 1 (proven ~9.7us): read both masks once, bit-pack, per-warp-chunk sums.
// ---------------------------------------------------------------------------
__global__ __launch_bounds__(NT) void k_pack(const uint32_t* __restrict__ ms,
                                             const uint32_t* __restrict__ ma) {
    int blk = blockIdx.x, tid = threadIdx.x;
    int lane = tid & 31, w = tid >> 5;
    size_t eA = (size_t)blk * TILE_P + (size_t)tid * 16;
    size_t eB = eA + 4096;
    const uint4* sA = reinterpret_cast<const uint4*>(ms + eA);
    const uint4* aA = reinterpret_cast<const uint4*>(ma + eA);
    const uint4* sB = reinterpret_cast<const uint4*>(ms + eB);
    const uint4* aB = reinterpret_cast<const uint4*>(ma + eB);

    unsigned bsA = 0, baA = 0, bsB = 0, baB = 0;
    #pragma unroll
    for (int i = 0; i < 4; i++) {
        uint4 s0 = sA[i], a0 = aA[i], s1 = sB[i], a1 = aB[i];
        bsA |= ((s0.x != 0u) << (i * 4)) | ((s0.y != 0u) << (i * 4 + 1)) |
               ((s0.z != 0u) << (i * 4 + 2)) | ((s0.w != 0u) << (i * 4 + 3));
        baA |= ((a0.x != 0u) << (i * 4)) | ((a0.y != 0u) << (i * 4 + 1)) |
               ((a0.z != 0u) << (i * 4 + 2)) | ((a0.w != 0u) << (i * 4 + 3));
        bsB |= ((s1.x != 0u) << (i * 4)) | ((s1.y != 0u) << (i * 4 + 1)) |
               ((s1.z != 0u) << (i * 4 + 2)) | ((s1.w != 0u) << (i * 4 + 3));
        baB |= ((a1.x != 0u) << (i * 4)) | ((a1.y != 0u) << (i * 4 + 1)) |
               ((a1.z != 0u) << (i * 4 + 2)) | ((a1.w != 0u) << (i * 4 + 3));
    }
    g_packed[blk * 512 + tid]       = bsA | (baA << 16);
    g_packed[blk * 512 + 256 + tid] = bsB | (baB << 16);

    int pA = __popc(bsA) | (__popc(baA) << 16);
    int pB = __popc(bsB) | (__popc(baB) << 16);
    #pragma unroll
    for (int o = 16; o > 0; o >>= 1) {
        pA += __shfl_xor_sync(0xffffffffu, pA, o);
        pB += __shfl_xor_sync(0xffffffffu, pB, o);
    }
    if (lane == 0) {
        g_wsum[blk * 16 + w]     = (unsigned)pA;
        g_wsum[blk * 16 + 8 + w] = (unsigned)pB;
    }
}

// ---------------------------------------------------------------------------
// Kernel 2 (proven ~2.5us): exclusive scan of 8192 packed warp sums.
// ---------------------------------------------------------------------------
__global__ __launch_bounds__(1024) void k_scan() {
    int tid = threadIdx.x, lane = tid & 31, w = tid >> 5;
    int ls[8], la_[8];
    int ss = 0, sa = 0;
    #pragma unroll
    for (int i = 0; i < 8; i++) {
        unsigned pw = g_wsum[tid * 8 + i];
        ls[i] = ss; la_[i] = sa;
        ss += (int)(pw & 0xffffu);
        sa += (int)(pw >> 16);
    }
    int is = ss, ia = sa;
    #pragma unroll
    for (int o = 1; o < 32; o <<= 1) {
        int t = __shfl_up_sync(0xffffffffu, is, o); if (lane >= o) is += t;
        t     = __shfl_up_sync(0xffffffffu, ia, o); if (lane >= o) ia += t;
    }
    __shared__ int ws[32], wa[32];
    if (lane == 31) { ws[w] = is; wa[w] = ia; }
    __syncthreads();
    if (w == 0) {
        int ts = ws[lane], ta = wa[lane];
        int js = ts, ja = ta;
        #pragma unroll
        for (int o = 1; o < 32; o <<= 1) {
            int t = __shfl_up_sync(0xffffffffu, js, o); if (lane >= o) js += t;
            t     = __shfl_up_sync(0xffffffffu, ja, o); if (lane >= o) ja += t;
        }
        ws[lane] = js - ts;
        wa[lane] = ja - ta;
    }
    __syncthreads();
    int base_s = ws[w] + is - ss;
    int base_a = wa[w] + ia - sa;
    #pragma unroll
    for (int i = 0; i < 8; i++) {
        g_woff_s[tid * 8 + i] = base_s + ls[i];
        g_woff_a[tid * 8 + i] = base_a + la_[i];
    }
}

// ---------------------------------------------------------------------------
// Kernel 3: expansion, warp-autonomous, barrier-free. Two half-passes of 2
// iterations each: PHASE A issues ALL gather loads (~40/thread) into regs,
// PHASE B does all stores. Per-iter bases precomputed (no loop-carried deps).
// ---------------------------------------------------------------------------
__global__ __launch_bounds__(NT) void k_main(
    const float* __restrict__ rgb, const float* __restrict__ ls,
    const float* __restrict__ la,  const float* __restrict__ idle_st,
    float* __restrict__ rgb_out, float* __restrict__ ls_out,
    float* __restrict__ la_out) {

    int blk = blockIdx.x, tid = threadIdx.x;
    int lane = tid & 31, w = tid >> 5;
    int gw = blk * 8 + w;

    unsigned wbits = g_packed[gw * 32 + lane];

    float idle   = idle_st[blk >> 5];
    float scale  = 1.0f - idle;
    float negadd = idle * NEG_IDLE_F;

    unsigned ms4[4], ma4[4];
    unsigned shift = (lane & 3) * 4;
    unsigned cnt_s = 0, cnt_a = 0;
    #pragma unroll
    for (int j = 0; j < 4; j++) {
        unsigned word = __shfl_sync(0xffffffffu, wbits, j * 8 + (lane >> 2));
        ms4[j] = (word >> shift) & 0xFu;
        ma4[j] = (word >> (16 + shift)) & 0xFu;
        cnt_s |= __popc(ms4[j]) << (j * 8);
        cnt_a |= __popc(ma4[j]) << (j * 8);
    }
    unsigned ip_s = cnt_s, ip_a = cnt_a;
    #pragma unroll
    for (int o = 1; o < 32; o <<= 1) {
        unsigned ts = __shfl_up_sync(0xffffffffu, ip_s, o);
        unsigned ta = __shfl_up_sync(0xffffffffu, ip_a, o);
        if (lane >= o) { ip_s += ts; ip_a += ta; }
    }
    unsigned tot_s = __shfl_sync(0xffffffffu, ip_s, 31);
    unsigned tot_a = __shfl_sync(0xffffffffu, ip_a, 31);
    unsigned ep_s = ip_s - cnt_s;
    unsigned ep_a = ip_a - cnt_a;

    // All 4 per-iter base offsets computed up front.
    int run_s = g_woff_s[gw];
    int run_a = g_woff_a[gw];
    int base_s[4], base_a[4];
    {
        int cs = 0, ca = 0;
        #pragma unroll
        for (int j = 0; j < 4; j++) {
            base_s[j] = run_s + cs + (int)((ep_s >> (j * 8)) & 0xffu);
            base_a[j] = run_a + ca + (int)((ep_a >> (j * 8)) & 0xffu);
            cs += (int)((tot_s >> (j * 8)) & 0xffu);
            ca += (int)((tot_a >> (j * 8)) & 0xffu);
        }
    }

    size_t wbase = (size_t)blk * TILE + (size_t)w * 512;

    #pragma unroll
    for (int h = 0; h < 2; h++) {
        float os[2][4], oa[2][4], ro[2][12];

        // ---- PHASE A: issue ALL loads for both iterations of this half ----
        #pragma unroll
        for (int jj = 0; jj < 2; jj++) {
            int j = h * 2 + jj;
            unsigned mS = ms4[j], mA = ma4[j];
            #pragma unroll
            for (int q = 0; q < 4; q++) {
                if ((mS >> q) & 1u) {
                    int idx = base_s[j] + __popc(mS & ((1u << q) - 1u));
                    os[jj][q] = __ldg(ls + idx);
                    const float* rp = rgb + (size_t)idx * 3;
                    ro[jj][q * 3 + 0] = __ldg(rp + 0);
                    ro[jj][q * 3 + 1] = __ldg(rp + 1);
                    ro[jj][q * 3 + 2] = __ldg(rp + 2);
                } else {
                    os[jj][q] = 0.0f;
                    ro[jj][q * 3 + 0] = 0.0f; ro[jj][q * 3 + 1] = 0.0f;
                    ro[jj][q * 3 + 2] = 0.0f;
                }
                if ((mA >> q) & 1u) {
                    int idx = base_a[j] + __popc(mA & ((1u << q) - 1u));
                    oa[jj][q] = __ldg(la + idx);
                } else {
                    oa[jj][q] = 0.0f;
                }
            }
        }

        // ---- PHASE B: scale + stores ----
        #pragma unroll
        for (int jj = 0; jj < 2; jj++) {
            int j = h * 2 + jj;
            unsigned mS = ms4[j], mA = ma4[j];
            size_t e0 = wbase + j * 128 + lane * 4;

            float fs[4], fa[4], fr[12];
            #pragma unroll
            for (int q = 0; q < 4; q++) {
                bool bs = (mS >> q) & 1u;
                bool ba = (mA >> q) & 1u;
                fs[q] = bs ? os[jj][q] * scale + negadd : NEG_FILL_F;
                fa[q] = ba ? oa[jj][q] * scale + negadd : NEG_FILL_F;
                fr[q * 3 + 0] = ro[jj][q * 3 + 0] * scale;
                fr[q * 3 + 1] = ro[jj][q * 3 + 1] * scale;
                fr[q * 3 + 2] = ro[jj][q * 3 + 2] * scale;
            }
            *reinterpret_cast<float4*>(ls_out + e0) = make_float4(fs[0], fs[1], fs[2], fs[3]);
            *reinterpret_cast<float4*>(la_out + e0) = make_float4(fa[0], fa[1], fa[2], fa[3]);
            float4* rout = reinterpret_cast<float4*>(rgb_out + e0 * 3);
            rout[0] = make_float4(fr[0], fr[1],  fr[2],  fr[3]);
            rout[1] = make_float4(fr[4], fr[5],  fr[6],  fr[7]);
            rout[2] = make_float4(fr[8], fr[9],  fr[10], fr[11]);
        }
    }
}

// ---------------------------------------------------------------------------
// Launch: 3 kernels (pack, scan, prefetch-batched expand). Graph-capturable.
// ---------------------------------------------------------------------------
extern "C" void kernel_launch(void* const* d_in, const int* in_sizes, int n_in,
                              void* d_out, int out_size) {
    const float*    rgb  = (const float*)d_in[0];
    const float*    ls   = (const float*)d_in[1];
    const float*    la   = (const float*)d_in[2];
    const uint32_t* msf  = (const uint32_t*)d_in[3];
    const uint32_t* maf  = (const uint32_t*)d_in[4];
    const float*    idle = (const float*)d_in[5];

    float* out     = (float*)d_out;
    float* rgb_out = out;
    float* ls_out  = out + (size_t)T_TOTAL * 3;
    float* la_out  = ls_out + T_TOTAL;

    k_pack<<<NBLK_P, NT>>>(msf, maf);
    k_scan<<<1, 1024>>>();
    k_main<<<NBLK, NT>>>(rgb, ls, la, idle, rgb_out, ls_out, la_out);
}